// round 10
// baseline (speedup 1.0000x reference)
#include <cuda_runtime.h>
#include <stdint.h>

#define BATCH   64
#define NPB     16384
#define QUARTER 4096
#define KSEL    1000
#define NCLS    80
#define NBIN    4096
#define CANDMAX 2048
#define NT      512

typedef unsigned long long u64;

// sorted top-1000 keys per quarter-batch (key = bits<<32 | (NPB-1-idx))
__device__ u64 g_cand[4 * BATCH][KSEL];

// out layout (f32): scores[64000*80] | batch_idx[64000] | boxes[64000*4]
#define BI_FOFF 5120000u
#define BX_FOFF 5184000u

// ---------------------------------------------------------------------------
// threshold search, 512 threads x 8 descending bins each
// ---------------------------------------------------------------------------
__device__ __forceinline__ void find_thresh512(
    const unsigned* hist, unsigned* warpsums, unsigned Kneed,
    unsigned* out_bin, unsigned* out_above, int tid)
{
    int base = NBIN - 1 - 8 * tid;
    unsigned c[8];
    unsigned tsum = 0;
    #pragma unroll
    for (int k = 0; k < 8; k++) { c[k] = hist[base - k]; tsum += c[k]; }

    unsigned v = tsum;
    #pragma unroll
    for (int d = 1; d < 32; d <<= 1) {
        unsigned n = __shfl_up_sync(0xFFFFFFFFu, v, d);
        if ((tid & 31) >= d) v += n;
    }
    if ((tid & 31) == 31) warpsums[tid >> 5] = v;   // 16 warps
    __syncthreads();
    if (tid < 32) {
        unsigned w = (tid < 16) ? warpsums[tid] : 0u;
        #pragma unroll
        for (int d = 1; d < 16; d <<= 1) {
            unsigned n = __shfl_up_sync(0xFFFFFFFFu, w, d);
            if (tid >= d) w += n;
        }
        if (tid < 16) warpsums[tid] = w;
    }
    __syncthreads();
    unsigned wpre = (tid >= 32) ? warpsums[(tid >> 5) - 1] : 0u;
    unsigned run  = wpre + v - tsum;               // count in strictly-higher bins

    #pragma unroll
    for (int k = 0; k < 8; k++) {
        if (run < Kneed && run + c[k] >= Kneed) {
            *out_bin = (unsigned)(base - k);
            *out_above = run;
        }
        run += c[k];
    }
    __syncthreads();
}

// ---------------------------------------------------------------------------
// Kernel 1: one CTA per QUARTER-batch (256 CTAs x 512 thr, occ 2/SM).
// Extract 4096 strided col-0 values, select quarter's top-1000, write sorted.
// ---------------------------------------------------------------------------
__global__ void __launch_bounds__(NT, 2)
quarter_select_kernel(const float* __restrict__ scores)
{
    __shared__ unsigned sh_hist[NBIN];      // 16 KB
    __shared__ u64      sh_cand[CANDMAX];   // 16 KB
    __shared__ unsigned sh_warpsums[16];
    __shared__ unsigned s_bin1, s_above1, s_bin2, s_above2, s_ncand;

    const int qb   = blockIdx.x;            // quarter id [0,256)
    const int b    = qb >> 2;
    const int rk   = qb & 3;
    const int tid  = threadIdx.x;
    const int lane = tid & 31;

    // ---- extract: 8 independent strided column-0 loads ----
    const float* colbase = scores + ((size_t)b * NPB + (size_t)rk * QUARTER) * NCLS;
    float raw[8];
    #pragma unroll
    for (int q = 0; q < 8; q++)
        raw[q] = __ldg(colbase + (size_t)(q * NT + tid) * NCLS);

    for (int i = tid; i < NBIN; i += NT) sh_hist[i] = 0u;
    if (tid == 0) s_ncand = 0u;
    __syncthreads();

    unsigned v[8];
    #pragma unroll
    for (int q = 0; q < 8; q++)
        v[q] = __float_as_uint(1.0f - raw[q]);   // positive floats: bits order-preserving

    // ---- level-1 histogram ----
    #pragma unroll
    for (int q = 0; q < 8; q++)
        atomicAdd(&sh_hist[v[q] >> 20], 1u);
    __syncthreads();
    find_thresh512(sh_hist, sh_warpsums, KSEL, &s_bin1, &s_above1, tid);
    unsigned bin1 = s_bin1, above1 = s_above1;

    // ---- level-2 histogram within bin1 ----
    for (int i = tid; i < NBIN; i += NT) sh_hist[i] = 0u;
    __syncthreads();
    #pragma unroll
    for (int q = 0; q < 8; q++)
        if ((v[q] >> 20) == bin1) atomicAdd(&sh_hist[(v[q] >> 8) & 0xFFFu], 1u);
    __syncthreads();
    find_thresh512(sh_hist, sh_warpsums, KSEL - above1, &s_bin2, &s_above2, tid);
    unsigned t24 = (bin1 << 12) | s_bin2;

    // ---- collect candidates (warp-aggregated) ----
    // key = (bits<<32) | (NPB-1-idx_in_batch): desc key == value desc, index asc
    #pragma unroll
    for (int q = 0; q < 8; q++) {
        unsigned u = v[q];
        bool pred = ((u >> 8) >= t24);
        unsigned mask = __ballot_sync(0xFFFFFFFFu, pred);
        if (mask) {
            int leader = __ffs(mask) - 1;
            unsigned basep = 0;
            if (lane == leader) basep = atomicAdd(&s_ncand, (unsigned)__popc(mask));
            basep = __shfl_sync(0xFFFFFFFFu, basep, leader);
            if (pred) {
                unsigned off = basep + (unsigned)__popc(mask & ((1u << lane) - 1u));
                if (off < CANDMAX) {
                    int idx = rk * QUARTER + q * NT + tid;   // index within batch
                    sh_cand[off] = ((u64)u << 32) | (u64)(unsigned)(NPB - 1 - idx);
                }
            }
        }
    }
    __syncthreads();
    unsigned nc = s_ncand < CANDMAX ? s_ncand : CANDMAX;
    unsigned SORT = (nc <= 1024u) ? 1024u : 2048u;
    for (unsigned i = tid; i < SORT; i += NT)
        if (i >= nc) sh_cand[i] = 0ull;

    // ---- bitonic sort descending (pairs looped over threads) ----
    for (unsigned k = 2; k <= SORT; k <<= 1) {
        for (unsigned j = k >> 1; j > 0; j >>= 1) {
            __syncthreads();
            for (unsigned t = (unsigned)tid; t < (SORT >> 1); t += NT) {
                unsigned mask = j - 1u;
                unsigned i = ((t & ~mask) << 1) | (t & mask);
                unsigned p = i | j;
                u64 a = sh_cand[i], c = sh_cand[p];
                bool desc = ((i & k) == 0u);
                if (desc ? (a < c) : (a > c)) { sh_cand[i] = c; sh_cand[p] = a; }
            }
        }
    }
    __syncthreads();

    // ---- write sorted top-1000 for this quarter ----
    for (int i = tid; i < KSEL; i += NT)
        g_cand[qb][i] = sh_cand[i];
}

// ---------------------------------------------------------------------------
// Kernel 2: 4 CTAs per batch (256 CTAs x 512 thr). 4-way sorted-list rank
// merge (exact, keys unique), then each CTA gathers 250 rows.
// ---------------------------------------------------------------------------
__device__ __forceinline__ unsigned count_greater(const u64* arr, u64 key)
{
    unsigned lo = 0, hi = KSEL;
    #pragma unroll
    for (int s = 0; s < 10; s++) {            // 2^10 = 1024 >= 1000
        if (lo < hi) {
            unsigned mid = (lo + hi) >> 1;
            if (arr[mid] > key) lo = mid + 1; else hi = mid;
        }
    }
    return lo;
}

__global__ void __launch_bounds__(NT, 2)
merge_gather_kernel(const float* __restrict__ scores,
                    const float* __restrict__ boxes,
                    float* __restrict__ out)
{
    __shared__ u64      shL[4][KSEL];         // 32 KB
    __shared__ unsigned sh_idx[KSEL];         // 4 KB: rank -> local row index

    const int b    = blockIdx.x >> 2;
    const int part = blockIdx.x & 3;
    const int tid  = threadIdx.x;

    #pragma unroll
    for (int l = 0; l < 4; l++)
        for (int i = tid; i < KSEL; i += NT)
            shL[l][i] = __ldg(&g_cand[4 * b + l][i]);
    __syncthreads();

    // exact global rank = own position + count-greater in the 3 other lists
    #pragma unroll
    for (int l = 0; l < 4; l++) {
        // two keys per thread per list, independent for ILP
        int i0 = tid, i1 = tid + NT;
        u64 k0 = shL[l][i0];
        u64 k1 = (i1 < KSEL) ? shL[l][i1] : 0ull;
        unsigned r0 = (unsigned)i0, r1 = (unsigned)i1;
        #pragma unroll
        for (int o = 1; o < 4; o++) {
            const u64* other = shL[(l + o) & 3];
            r0 += count_greater(other, k0);
            r1 += count_greater(other, k1);
        }
        if (r0 < KSEL) sh_idx[r0] = (NPB - 1u) - (unsigned)(k0 & 0xFFFFull);
        if (i1 < KSEL && r1 < KSEL)
            sh_idx[r1] = (NPB - 1u) - (unsigned)(k1 & 0xFFFFull);
    }
    __syncthreads();

    // ---- gather ranks [part*250, part*250+250), 8 threads per row ----
    const int rbase = part * 250;
    const int q  = tid & 7;
    const int rw = tid >> 3;                  // 0..63
    #pragma unroll 1
    for (int it = 0; it < 2; it++) {
        int lA = it * 64 + rw;                // 0..63 / 64..127: always < 250
        int lB = lA + 128;                    // 128..191 / 192..255
        bool vB = lB < 250;
        unsigned ilA = sh_idx[rbase + lA];
        unsigned ilB = sh_idx[rbase + (vB ? lB : lA)];
        const float4* sA = (const float4*)(scores + ((size_t)b * NPB + ilA) * NCLS);
        const float4* sB = (const float4*)(scores + ((size_t)b * NPB + ilB) * NCLS);
        float4 a0 = __ldg(sA + q);
        float4 b0 = __ldg(sB + q);
        float4 a1 = __ldg(sA + q + 8);
        float4 b1 = __ldg(sB + q + 8);
        float4 a2, b2;
        if (q < 4) { a2 = __ldg(sA + 16 + q); b2 = __ldg(sB + 16 + q); }

        int rowA = rbase + lA;
        float4* dA = (float4*)(out + ((size_t)b * KSEL + rowA) * NCLS);
        dA[q]     = a0;
        dA[q + 8] = a1;
        if (q < 4) dA[16 + q] = a2;
        if (vB) {
            int rowB = rbase + lB;
            float4* dB = (float4*)(out + ((size_t)b * KSEL + rowB) * NCLS);
            dB[q]     = b0;
            dB[q + 8] = b1;
            if (q < 4) dB[16 + q] = b2;
        }
    }
    // boxes + batch index: one thread per row (250 rows per CTA)
    if (tid < 250) {
        int row = rbase + tid;
        unsigned il = sh_idx[row];
        size_t g = (size_t)b * NPB + il;
        size_t r = (size_t)b * KSEL + (size_t)row;
        float4 bx = __ldg((const float4*)(boxes + g * 4));
        *(float4*)(out + BX_FOFF + r * 4) = bx;
        out[BI_FOFF + r] = (float)b;
    }
}

extern "C" void kernel_launch(void* const* d_in, const int* in_sizes, int n_in,
                              void* d_out, int out_size)
{
    const float* scores = (const float*)d_in[0];
    const float* boxes  = (const float*)d_in[2];
    float* out = (float*)d_out;

    quarter_select_kernel<<<4 * BATCH, NT>>>(scores);
    merge_gather_kernel<<<4 * BATCH, NT>>>(scores, boxes, out);
}

// round 11
// speedup vs baseline: 1.2549x; 1.2549x over previous
#include <cuda_runtime.h>
#include <stdint.h>

#define BATCH   64
#define NPB     16384
#define HALF    8192
#define KSEL    1000
#define NCLS    80
#define NBIN    4096
#define CANDMAX 2048

typedef unsigned long long u64;

__device__ unsigned g_fg[BATCH * NPB];          // fg float bits per row (4 MB)
__device__ u64 g_cand[2 * BATCH][KSEL];          // sorted top-1000 per half

// out layout (f32): scores[64000*80] | batch_idx[64000] | boxes[64000*4]
#define BI_FOFF 5120000u
#define BX_FOFF 5184000u

// ---------------------------------------------------------------------------
// K0: strided column-0 read, coalesced write of fg bits. (R2-proven 5.8 TB/s)
// ---------------------------------------------------------------------------
__global__ void __launch_bounds__(256)
extract_kernel(const float* __restrict__ scores)
{
    int base = blockIdx.x * 2048;
    int tid  = threadIdx.x;
    #pragma unroll 8
    for (int k = 0; k < 8; k++) {
        int r = base + k * 256 + tid;
        float s = __ldg(scores + (size_t)r * NCLS);
        g_fg[r] = __float_as_uint(1.0f - s);   // positive floats: bits order-preserving
    }
}

// ---------------------------------------------------------------------------
// threshold search over 4096-bin histogram (descending), warp-shuffle scan
// (1024 threads, 4 bins each)
// ---------------------------------------------------------------------------
__device__ __forceinline__ void find_thresh(
    const unsigned* hist, unsigned* warpsums, unsigned Kneed,
    unsigned* out_bin, unsigned* out_above, int tid)
{
    int base = NBIN - 1 - 4 * tid;
    unsigned c0 = hist[base],     c1 = hist[base - 1];
    unsigned c2 = hist[base - 2], c3 = hist[base - 3];
    unsigned tsum = c0 + c1 + c2 + c3;

    unsigned v = tsum;
    #pragma unroll
    for (int d = 1; d < 32; d <<= 1) {
        unsigned n = __shfl_up_sync(0xFFFFFFFFu, v, d);
        if ((tid & 31) >= d) v += n;
    }
    if ((tid & 31) == 31) warpsums[tid >> 5] = v;
    __syncthreads();
    if (tid < 32) {
        unsigned w = warpsums[tid];
        #pragma unroll
        for (int d = 1; d < 32; d <<= 1) {
            unsigned n = __shfl_up_sync(0xFFFFFFFFu, w, d);
            if (tid >= d) w += n;
        }
        warpsums[tid] = w;
    }
    __syncthreads();
    unsigned wpre = (tid >= 32) ? warpsums[(tid >> 5) - 1] : 0u;
    unsigned run  = wpre + v - tsum;               // count in strictly-higher bins

    if (run < Kneed && run + c0 >= Kneed) { *out_bin = (unsigned)base;     *out_above = run; }
    run += c0;
    if (run < Kneed && run + c1 >= Kneed) { *out_bin = (unsigned)base - 1; *out_above = run; }
    run += c1;
    if (run < Kneed && run + c2 >= Kneed) { *out_bin = (unsigned)base - 2; *out_above = run; }
    run += c2;
    if (run < Kneed && run + c3 >= Kneed) { *out_bin = (unsigned)base - 3; *out_above = run; }
    __syncthreads();
}

// ---------------------------------------------------------------------------
// K1: one CTA per HALF-batch (128 CTAs x 1024). Coalesced reload of fg bits,
// 2-level radix threshold, collect, bitonic sort, write sorted top-1000.
// ---------------------------------------------------------------------------
__global__ void __launch_bounds__(1024, 1)
half_select_kernel()
{
    __shared__ unsigned sh_hist[NBIN];      // 16 KB
    __shared__ u64      sh_cand[CANDMAX];   // 16 KB
    __shared__ unsigned sh_warpsums[32];
    __shared__ unsigned s_bin1, s_above1, s_bin2, s_above2, s_ncand;

    const int hb   = blockIdx.x;            // half-batch id [0,128)
    const int b    = hb >> 1;
    const int rk   = hb & 1;
    const int tid  = threadIdx.x;
    const int lane = tid & 31;

    // ---- coalesced load of 8192 fg bits (uint4) ----
    unsigned v[8];
    const uint4* src = (const uint4*)(g_fg + b * NPB + rk * HALF);
    #pragma unroll
    for (int c = 0; c < 2; c++) {
        uint4 x = __ldg(src + c * 1024 + tid);
        v[c * 4 + 0] = x.x; v[c * 4 + 1] = x.y;
        v[c * 4 + 2] = x.z; v[c * 4 + 3] = x.w;
    }

    for (int i = tid; i < NBIN; i += 1024) sh_hist[i] = 0u;
    if (tid == 0) s_ncand = 0u;
    __syncthreads();

    // ---- level-1 histogram: top 12 bits ----
    #pragma unroll
    for (int q = 0; q < 8; q++)
        atomicAdd(&sh_hist[v[q] >> 20], 1u);
    __syncthreads();
    find_thresh(sh_hist, sh_warpsums, KSEL, &s_bin1, &s_above1, tid);
    unsigned bin1 = s_bin1, above1 = s_above1;

    // ---- level-2 histogram within bin1 ----
    for (int i = tid; i < NBIN; i += 1024) sh_hist[i] = 0u;
    __syncthreads();
    #pragma unroll
    for (int q = 0; q < 8; q++)
        if ((v[q] >> 20) == bin1) atomicAdd(&sh_hist[(v[q] >> 8) & 0xFFFu], 1u);
    __syncthreads();
    find_thresh(sh_hist, sh_warpsums, KSEL - above1, &s_bin2, &s_above2, tid);
    unsigned t24 = (bin1 << 12) | s_bin2;

    // ---- collect candidates (warp-aggregated) ----
    // element index within batch: rk*HALF + (c*1024+tid)*4 + q  (uint4 order)
    // key = (bits<<32) | (NPB-1-idx): desc key == value desc, index asc
    #pragma unroll
    for (int c = 0; c < 2; c++) {
        #pragma unroll
        for (int q = 0; q < 4; q++) {
            unsigned u = v[c * 4 + q];
            bool pred = ((u >> 8) >= t24);
            unsigned mask = __ballot_sync(0xFFFFFFFFu, pred);
            if (mask) {
                int leader = __ffs(mask) - 1;
                unsigned basep = 0;
                if (lane == leader) basep = atomicAdd(&s_ncand, (unsigned)__popc(mask));
                basep = __shfl_sync(0xFFFFFFFFu, basep, leader);
                if (pred) {
                    unsigned off = basep + (unsigned)__popc(mask & ((1u << lane) - 1u));
                    if (off < CANDMAX) {
                        int idx = rk * HALF + (c * 1024 + tid) * 4 + q;
                        sh_cand[off] = ((u64)u << 32) | (u64)(unsigned)(NPB - 1 - idx);
                    }
                }
            }
        }
    }
    __syncthreads();
    unsigned nc = s_ncand < CANDMAX ? s_ncand : CANDMAX;
    unsigned SORT = (nc <= 1024u) ? 1024u : 2048u;
    for (unsigned i = tid; i < SORT; i += 1024)
        if (i >= nc) sh_cand[i] = 0ull;

    // ---- bitonic sort descending ----
    for (unsigned k = 2; k <= SORT; k <<= 1) {
        for (unsigned j = k >> 1; j > 0; j >>= 1) {
            __syncthreads();
            if ((unsigned)tid < (SORT >> 1)) {
                unsigned mask = j - 1u;
                unsigned i = (((unsigned)tid & ~mask) << 1) | ((unsigned)tid & mask);
                unsigned p = i | j;
                u64 a = sh_cand[i], c = sh_cand[p];
                bool desc = ((i & k) == 0u);
                if (desc ? (a < c) : (a > c)) { sh_cand[i] = c; sh_cand[p] = a; }
            }
        }
    }
    __syncthreads();

    if (tid < KSEL) g_cand[hb][tid] = sh_cand[tid];
}

// ---------------------------------------------------------------------------
// K2: 4 CTAs per batch (256 CTAs x 512). 2-way sorted-list rank merge
// (exact, keys unique), then each CTA gathers 250 rows.
// ---------------------------------------------------------------------------
__device__ __forceinline__ unsigned count_greater(const u64* arr, u64 key)
{
    unsigned lo = 0, hi = KSEL;
    #pragma unroll
    for (int s = 0; s < 10; s++) {            // 2^10 = 1024 >= 1000
        if (lo < hi) {
            unsigned mid = (lo + hi) >> 1;
            if (arr[mid] > key) lo = mid + 1; else hi = mid;
        }
    }
    return lo;
}

__global__ void __launch_bounds__(512)
merge_gather_kernel(const float* __restrict__ scores,
                    const float* __restrict__ boxes,
                    float* __restrict__ out)
{
    __shared__ u64      shA[KSEL];            // 8 KB
    __shared__ u64      shB[KSEL];            // 8 KB
    __shared__ unsigned sh_idx[KSEL];         // 4 KB: rank -> local row index

    const int b    = blockIdx.x >> 2;
    const int part = blockIdx.x & 3;
    const int tid  = threadIdx.x;

    for (int i = tid; i < KSEL; i += 512) {
        shA[i] = __ldg(&g_cand[2 * b][i]);
        shB[i] = __ldg(&g_cand[2 * b + 1][i]);
    }
    __syncthreads();

    // exact global rank = own position + count-greater in the other list
    #pragma unroll
    for (int h = 0; h < 2; h++) {
        int i = tid + h * 512;
        if (i < KSEL) {
            u64 kA = shA[i];
            unsigned rA = (unsigned)i + count_greater(shB, kA);
            if (rA < KSEL) sh_idx[rA] = (NPB - 1u) - (unsigned)(kA & 0xFFFFull);
            u64 kB = shB[i];
            unsigned rB = (unsigned)i + count_greater(shA, kB);
            if (rB < KSEL) sh_idx[rB] = (NPB - 1u) - (unsigned)(kB & 0xFFFFull);
        }
    }
    __syncthreads();

    // ---- gather ranks [part*250, part*250+250), 8 threads per row ----
    const int rbase = part * 250;
    const int q  = tid & 7;
    const int rw = tid >> 3;                  // 0..63
    #pragma unroll 1
    for (int it = 0; it < 2; it++) {
        int lA = it * 64 + rw;                // 0..127: always < 250
        int lB = lA + 128;                    // 128..255: valid if < 250
        bool vB = lB < 250;
        unsigned ilA = sh_idx[rbase + lA];
        unsigned ilB = sh_idx[rbase + (vB ? lB : lA)];
        const float4* sA = (const float4*)(scores + ((size_t)b * NPB + ilA) * NCLS);
        const float4* sB = (const float4*)(scores + ((size_t)b * NPB + ilB) * NCLS);
        float4 a0 = __ldg(sA + q);
        float4 b0 = __ldg(sB + q);
        float4 a1 = __ldg(sA + q + 8);
        float4 b1 = __ldg(sB + q + 8);
        float4 a2, b2;
        if (q < 4) { a2 = __ldg(sA + 16 + q); b2 = __ldg(sB + 16 + q); }

        int rowA = rbase + lA;
        float4* dA = (float4*)(out + ((size_t)b * KSEL + rowA) * NCLS);
        dA[q]     = a0;
        dA[q + 8] = a1;
        if (q < 4) dA[16 + q] = a2;
        if (vB) {
            int rowB = rbase + lB;
            float4* dB = (float4*)(out + ((size_t)b * KSEL + rowB) * NCLS);
            dB[q]     = b0;
            dB[q + 8] = b1;
            if (q < 4) dB[16 + q] = b2;
        }
    }
    // boxes + batch index: one thread per row (250 rows per CTA)
    if (tid < 250) {
        int row = rbase + tid;
        unsigned il = sh_idx[row];
        size_t g = (size_t)b * NPB + il;
        size_t r = (size_t)b * KSEL + (size_t)row;
        float4 bx = __ldg((const float4*)(boxes + g * 4));
        *(float4*)(out + BX_FOFF + r * 4) = bx;
        out[BI_FOFF + r] = (float)b;
    }
}

extern "C" void kernel_launch(void* const* d_in, const int* in_sizes, int n_in,
                              void* d_out, int out_size)
{
    const float* scores = (const float*)d_in[0];
    const float* boxes  = (const float*)d_in[2];
    float* out = (float*)d_out;

    extract_kernel<<<(BATCH * NPB) / 2048, 256>>>(scores);
    half_select_kernel<<<2 * BATCH, 1024>>>();
    merge_gather_kernel<<<4 * BATCH, 512>>>(scores, boxes, out);
}